// round 16
// baseline (speedup 1.0000x reference)
#include <cuda_runtime.h>
#include <math.h>
#include <cstdint>

// ---------------- problem constants ----------------
#define N_TOT   65536      // B*H*W
#define K_CB    512
#define C_DIM   64
#define B_DIM   64
#define HW      1024

#define TM      64         // rows per tile (16 warps x 4 rows)
#define THREADS 512
#define NWARP   16
#define NTILES  1024
#define NCTAS   152        // persistent, 1 CTA/SM
#define WROW    514        // wT row stride (floats)

// output layout (floats), concatenation of the reference tuple
#define Q_OFF     0ULL
#define LOSS_OFF  4194304ULL
#define PERP_OFF  4194368ULL
#define ENC_OFF   4194369ULL
#define EIDX_OFF  37748801ULL
#define DIST_OFF  37814337ULL
#define OUT_TOTAL 71368769

// smem layout (float indices)
#define SM_WT   0                      // wT[64][514] = 32896 floats
#define SM_XW   32896                  // per-warp raw x slices: 16 w x 2 bufs x 256 = 8192
#define SM_XD   (SM_XW + 8192)         // per-warp duplicated pairs: 16 w x 512 = 8192
#define SM_WN   (SM_XD + 8192)         // wnorm[512]
#define SM_RED  (SM_WN + 512)          // float red[512] (finish only)
#define SM_TOTF (SM_RED + 512)
#define SMEM_BYTES (SM_TOTF * 4)       // ~200 KB -> 1 CTA/SM

__device__ float g_lp[NTILES * NWARP]; // per (tile, warp) loss partial
__device__ int   g_hist[K_CB];         // zero at load; last CTA re-zeroes each launch
__device__ int   g_done;               // arrival ticket; last CTA resets

typedef unsigned long long ull;

// ---------------- helpers ----------------
__device__ __forceinline__ void fma2(ull &d, ull a, ull b) {
    asm("fma.rn.f32x2 %0, %1, %2, %3;" : "=l"(d) : "l"(a), "l"(b), "l"(d));
}
__device__ __forceinline__ void unpack2(ull v, float &lo, float &hi) {
    asm("mov.b64 {%0, %1}, %2;" : "=f"(lo), "=f"(hi) : "l"(v));
}
__device__ __forceinline__ uint32_t smem_u32(const void* p) {
    uint32_t a;
    asm("{ .reg .u64 t; cvta.to.shared.u64 t, %1; cvt.u32.u64 %0, t; }" : "=r"(a) : "l"(p));
    return a;
}
#define CP_ASYNC16(sa, gp) asm volatile("cp.async.cg.shared.global [%0], [%1], 16;" :: "r"(sa), "l"(gp))
#define CP_COMMIT()        asm volatile("cp.async.commit_group;" ::: "memory")
#define CP_WAIT1()         asm volatile("cp.async.wait_group 1;" ::: "memory")
#define CP_WAIT0()         asm volatile("cp.async.wait_group 0;" ::: "memory")

// ---------------- single persistent kernel, free-running warps ----------------
extern "C" __global__ void __launch_bounds__(THREADS, 1)
vq_all(const float* __restrict__ inputs, const float* __restrict__ weight,
       float* __restrict__ out)
{
    extern __shared__ float smem[];
    float* wT    = smem + SM_WT;       // wT[c][k]
    float* wnorm = smem + SM_WN;
    float* red   = smem + SM_RED;

    const int tid  = threadIdx.x;
    const int warp = tid >> 5;         // warp owns rows 4*warp .. 4*warp+3 of every tile
    const int lane = tid & 31;
    const int cta  = blockIdx.x;

    float* xw_base = smem + SM_XW + warp * 512;         // 2 raw slices x 256 floats
    float* dupf    = smem + SM_XD + warp * 512;         // duplicated pairs: [c][4 pairs]
    const uint32_t xw_sa = smem_u32(xw_base);

    // per-thread cp.async channels: this thread copies c = lane and c = lane+32
    const int c0 = lane, c1 = lane + 32;

    // ---- prefetch first tile's slice into buf 0 ----
    {
        const int t0 = cta;
        const float* src = inputs + (size_t)(t0 >> 4) * (C_DIM * HW)
                         + (t0 & 15) * 64 + 4 * warp;
        CP_ASYNC16(xw_sa + (uint32_t)(c0 * 4) * 4, src + (size_t)c0 * HW);
        CP_ASYNC16(xw_sa + (uint32_t)(c1 * 4) * 4, src + (size_t)c1 * HW);
        CP_COMMIT();
    }

    // ---- one-time: weight transpose + wnorm (the only CTA barriers) ----
    for (int i = tid; i < K_CB * C_DIM; i += THREADS) {
        int k = i >> 6, c = i & 63;
        wT[c * WROW + k] = weight[i];
    }
    __syncthreads();
    {
        float s = 0.f;
        #pragma unroll
        for (int c = 0; c < C_DIM; c++) { float w = wT[c * WROW + tid]; s = fmaf(w, w, s); }
        wnorm[tid] = s;
    }
    __syncthreads();

    // ---- per-warp persistent tile loop (no CTA barriers inside) ----
    int buf = 0;
    for (int t = cta; t < NTILES; t += NCTAS) {
        // prefetch next tile's slice into the other buffer
        {
            int tn = t + NCTAS; if (tn >= NTILES) tn = 0;
            const float* src = inputs + (size_t)(tn >> 4) * (C_DIM * HW)
                             + (tn & 15) * 64 + 4 * warp;
            uint32_t dst = xw_sa + (uint32_t)((buf ^ 1) * 256) * 4;
            CP_ASYNC16(dst + (uint32_t)(c0 * 4) * 4, src + (size_t)c0 * HW);
            CP_ASYNC16(dst + (uint32_t)(c1 * 4) * 4, src + (size_t)c1 * HW);
            CP_COMMIT();
        }
        CP_WAIT1();                    // this thread's copies for current buffer done
        __syncwarp();                  // all lanes' copies visible warp-wide

        const float* slice = xw_base + buf * 256;   // raw [c][4] floats

        // duplicate own slice into {x,x} pairs (kills pack2 MOVs in the mainloop)
        {
            float2* xd = (float2*)dupf;
            #pragma unroll
            for (int i = 0; i < 8; i++) {
                const int j = lane + 32 * i;           // 256 entries
                float v = slice[j];
                xd[j] = make_float2(v, v);
            }
        }
        __syncwarp();                  // dup visible to all lanes (broadcast reads)

        // xnorm for own rows: lane r (<4) computes row r (sequential fmaf rounding)
        float xn_own = 0.f;
        if (lane < 4) {
            #pragma unroll
            for (int c = 0; c < C_DIM; c++) {
                float x = dupf[c * 8 + 2 * lane];
                xn_own = fmaf(x, x, xn_own);
            }
        }

        // ---- mainloop: 4 rows x 16 codes per lane; codes k = 2*lane + 64*j ----
        ull acc[4][8];
        #pragma unroll
        for (int r = 0; r < 4; r++)
            #pragma unroll
            for (int j = 0; j < 8; j++) acc[r][j] = 0ULL;

        const ull* bbase = (const ull*)(wT + 2 * lane);
        const ulonglong2* arow = (const ulonglong2*)dupf;   // 4 pairs per c = 2 ull2

        #pragma unroll 4
        for (int c = 0; c < C_DIM; c++) {
            ulonglong2 v0 = arow[c * 2];                     // pairs {r0,r0},{r1,r1}
            ulonglong2 v1 = arow[c * 2 + 1];                 // pairs {r2,r2},{r3,r3}
            ull a0 = v0.x, a1 = v0.y, a2 = v1.x, a3 = v1.y;
            const ull* bp = bbase + (size_t)c * (WROW / 2);
            ull bb[8];
            #pragma unroll
            for (int j = 0; j < 8; j++) bb[j] = bp[32 * j];  // conflict-free LDS.64
            #pragma unroll
            for (int j = 0; j < 8; j++) {
                fma2(acc[0][j], a0, bb[j]);
                fma2(acc[1][j], a1, bb[j]);
                fma2(acc[2][j], a2, bb[j]);
                fma2(acc[3][j], a3, bb[j]);
            }
        }

        const int n0   = t * TM + 4 * warp;       // first row owned by this warp
        const int bimg = t >> 4;
        const int p0   = (t & 15) * 64 + 4 * warp;

        // ---- epilogue: distances (reference rounding) + full-K warp argmin ----
        const float INF = __int_as_float(0x7f800000);
        int   bi_r[4];
        #pragma unroll
        for (int r = 0; r < 4; r++) {
            const int n = n0 + r;
            const float xn = __shfl_sync(0xffffffffu, xn_own, r);

            float best = INF; int bidx = 0;
            float* dptr = out + DIST_OFF + (size_t)n * K_CB;
            #pragma unroll
            for (int j = 0; j < 8; j++) {
                float zlo, zhi; unpack2(acc[r][j], zlo, zhi);
                const int k0 = 2 * lane + 64 * j;
                const float2 wn2 = *(const float2*)(wnorm + k0);  // LDS.64 aligned
                float dlo = (xn + wn2.x) - 2.0f * zlo;
                float dhi = (xn + wn2.y) - 2.0f * zhi;
                __stcs(dptr + k0,     dlo);                       // coalesced pairs
                __stcs(dptr + k0 + 1, dhi);
                if (dlo < best) { best = dlo; bidx = k0; }        // ascending k, strict '<'
                if (dhi < best) { best = dhi; bidx = k0 + 1; }    // -> lowest index on ties
            }
            #pragma unroll
            for (int off = 16; off > 0; off >>= 1) {
                float ob = __shfl_xor_sync(0xffffffffu, best, off);
                int   oi = __shfl_xor_sync(0xffffffffu, bidx, off);
                if (ob < best || (ob == best && oi < bidx)) { best = ob; bidx = oi; }
            }
            bi_r[r] = bidx;                                      // all lanes agree
            if (lane == 0) {
                out[EIDX_OFF + (size_t)n] = (float)bidx;
                atomicAdd(&g_hist[bidx], 1);                     // order-independent
            }
        }

        // ---- encodings one-hot for own 4 rows: float4 interior + 4 scalars ----
        {
            float* ebase = out + ENC_OFF + (size_t)n0 * K_CB;
            #pragma unroll
            for (int r = 0; r < 4; r++) {
                const int sv = bi_r[r];
                float* rbase = ebase + (size_t)r * K_CB;
                #pragma unroll
                for (int m = lane; m < 127; m += 32) {
                    const int k = 3 + 4 * m;
                    float4 v;
                    v.x = (sv == k)     ? 1.0f : 0.0f;
                    v.y = (sv == k + 1) ? 1.0f : 0.0f;
                    v.z = (sv == k + 2) ? 1.0f : 0.0f;
                    v.w = (sv == k + 3) ? 1.0f : 0.0f;
                    __stcs((float4*)(rbase + k), v);   // 16B aligned (ENC_OFF odd + 3)
                }
                if (lane < 3)       rbase[lane] = (sv == lane) ? 1.0f : 0.0f;
                else if (lane == 3) rbase[511]  = (sv == 511)  ? 1.0f : 0.0f;
            }
        }

        // ---- q_out for own rows (x + (q - x)) + loss partial; 2 c per lane ----
        float s = 0.f;
        float* qbase = out + (size_t)bimg * (C_DIM * HW) + p0;
        #pragma unroll
        for (int cc = 0; cc < 2; cc++) {
            const int c = cc ? c1 : c0;
            // duplicated layout: rows at even positions of dupf[c*8 ..]
            float4 fa = *(const float4*)(dupf + c * 8);       // (r0, r0, r1, r1)
            float4 fb = *(const float4*)(dupf + c * 8 + 4);   // (r2, r2, r3, r3)
            const float* wrow = wT + c * WROW;
            float d0 = wrow[bi_r[0]] - fa.x;
            float d1 = wrow[bi_r[1]] - fa.z;
            float d2 = wrow[bi_r[2]] - fb.x;
            float d3 = wrow[bi_r[3]] - fb.z;
            float4 o;
            o.x = fa.x + d0; o.y = fa.z + d1; o.z = fb.x + d2; o.w = fb.z + d3;
            __stcs((float4*)(qbase + (size_t)c * HW), o);     // 16B aligned
            s = fmaf(d0, d0, s); s = fmaf(d1, d1, s);
            s = fmaf(d2, d2, s); s = fmaf(d3, d3, s);
        }
        #pragma unroll
        for (int off = 16; off > 0; off >>= 1) s += __shfl_xor_sync(0xffffffffu, s, off);
        if (lane == 0) g_lp[t * NWARP + warp] = s;

        __syncwarp();                  // dup/slice reads done before next-iter reuse
        buf ^= 1;
    }
    CP_WAIT0();                        // drain dangling prefetch

    // ---- fused finish: last CTA computes loss + perplexity ----
    __syncthreads();
    __shared__ int s_last;
    if (tid == 0) {
        __threadfence();
        s_last = (atomicAdd(&g_done, 1) == NCTAS - 1);
    }
    __syncthreads();
    if (s_last) {
        if (tid == 0) g_done = 0;                 // reset for graph replay
        if (tid < B_DIM) {
            float s = 0.f;
            #pragma unroll
            for (int j = 0; j < 16; j++)          // tiles of batch, fixed order
                #pragma unroll
                for (int w = 0; w < NWARP; w++)   // warp partials, fixed order
                    s += g_lp[(tid * 16 + j) * NWARP + w];
            out[LOSS_OFF + tid] = 1.25f * (s * (1.0f / 65536.0f));
        }
        int h = g_hist[tid];
        g_hist[tid] = 0;                          // restore zero invariant
        float p = (float)h * (1.0f / 65536.0f);
        red[tid] = -p * logf(p + 1e-10f);
        __syncthreads();
        #pragma unroll
        for (int off = 256; off > 0; off >>= 1) {
            if (tid < off) red[tid] += red[tid + off];
            __syncthreads();
        }
        if (tid == 0) out[PERP_OFF] = expf(red[0]);
    }
}

// ---------------- launch ----------------
extern "C" void kernel_launch(void* const* d_in, const int* in_sizes, int n_in,
                              void* d_out, int out_size)
{
    const float* inputs = (const float*)d_in[0];
    const float* weight = (const float*)d_in[1];
    float* out = (float*)d_out;

    if (out_size != OUT_TOTAL) return;

    cudaFuncSetAttribute(vq_all, cudaFuncAttributeMaxDynamicSharedMemorySize, SMEM_BYTES);

    vq_all<<<NCTAS, THREADS, SMEM_BYTES>>>(inputs, weight, out);
}

// round 17
// speedup vs baseline: 1.1228x; 1.1228x over previous
#include <cuda_runtime.h>
#include <math.h>
#include <cstdint>

// ---------------- problem constants ----------------
#define N_TOT   65536      // B*H*W
#define K_CB    512
#define C_DIM   64
#define B_DIM   64
#define HW      1024

#define TM      64         // rows per tile (16 warps x 4 rows)
#define THREADS 512
#define NWARP   16
#define NTILES  1024
#define NCTAS   152        // persistent, 1 CTA/SM
#define WROW    514        // wT row stride (floats)

// output layout (floats), concatenation of the reference tuple
#define Q_OFF     0ULL
#define LOSS_OFF  4194304ULL
#define PERP_OFF  4194368ULL
#define ENC_OFF   4194369ULL
#define EIDX_OFF  37748801ULL
#define DIST_OFF  37814337ULL
#define OUT_TOTAL 71368769

// smem layout (float indices)
#define SM_WT   0                      // wT[64][514] = 32896 floats
#define SM_XW   32896                  // per-warp x slices: 16 warps x 2 bufs x 256 = 8192
#define SM_WN   (SM_XW + 8192)         // wnorm[512]
#define SM_RED  (SM_WN + 512)          // float red[512] (finish only)
#define SM_TOTF (SM_RED + 512)
#define SMEM_BYTES (SM_TOTF * 4)       // ~168 KB -> 1 CTA/SM

__device__ float g_lp[NTILES * NWARP]; // per (tile, warp) loss partial
__device__ int   g_hist[K_CB];         // zero at load; last CTA re-zeroes each launch
__device__ int   g_done;               // arrival ticket; last CTA resets

typedef unsigned long long ull;

// ---------------- helpers ----------------
__device__ __forceinline__ ull pack2(float x) {
    ull r; asm("mov.b64 %0, {%1, %1};" : "=l"(r) : "f"(x)); return r;
}
__device__ __forceinline__ void fma2(ull &d, ull a, ull b) {
    asm("fma.rn.f32x2 %0, %1, %2, %3;" : "=l"(d) : "l"(a), "l"(b), "l"(d));
}
__device__ __forceinline__ void unpack2(ull v, float &lo, float &hi) {
    asm("mov.b64 {%0, %1}, %2;" : "=f"(lo), "=f"(hi) : "l"(v));
}
__device__ __forceinline__ uint32_t smem_u32(const void* p) {
    uint32_t a;
    asm("{ .reg .u64 t; cvta.to.shared.u64 t, %1; cvt.u32.u64 %0, t; }" : "=r"(a) : "l"(p));
    return a;
}
#define CP_ASYNC16(sa, gp) asm volatile("cp.async.cg.shared.global [%0], [%1], 16;" :: "r"(sa), "l"(gp))
#define CP_COMMIT()        asm volatile("cp.async.commit_group;" ::: "memory")
#define CP_WAIT1()         asm volatile("cp.async.wait_group 1;" ::: "memory")
#define CP_WAIT0()         asm volatile("cp.async.wait_group 0;" ::: "memory")

// ---------------- single persistent kernel, free-running warps ----------------
extern "C" __global__ void __launch_bounds__(THREADS, 1)
vq_all(const float* __restrict__ inputs, const float* __restrict__ weight,
       float* __restrict__ out)
{
    extern __shared__ float smem[];
    float* wT    = smem + SM_WT;       // wT[c][k]
    float* wnorm = smem + SM_WN;
    float* red   = smem + SM_RED;

    const int tid  = threadIdx.x;
    const int warp = tid >> 5;         // warp owns rows 4*warp .. 4*warp+3 of every tile
    const int lane = tid & 31;
    const int cta  = blockIdx.x;

    float* xw_base = smem + SM_XW + warp * 512;         // 2 slices x 256 floats
    const uint32_t xw_sa = smem_u32(xw_base);

    // per-thread cp.async channels: this thread copies c = lane and c = lane+32
    const int c0 = lane, c1 = lane + 32;

    // ---- prefetch first tile's slice into buf 0 ----
    {
        const int t0 = cta;
        const float* src = inputs + (size_t)(t0 >> 4) * (C_DIM * HW)
                         + (t0 & 15) * 64 + 4 * warp;
        CP_ASYNC16(xw_sa + (uint32_t)(c0 * 4) * 4, src + (size_t)c0 * HW);
        CP_ASYNC16(xw_sa + (uint32_t)(c1 * 4) * 4, src + (size_t)c1 * HW);
        CP_COMMIT();
    }

    // ---- one-time: weight transpose + wnorm (the only CTA barriers) ----
    for (int i = tid; i < K_CB * C_DIM; i += THREADS) {
        int k = i >> 6, c = i & 63;
        wT[c * WROW + k] = weight[i];
    }
    __syncthreads();
    {
        float s = 0.f;
        #pragma unroll
        for (int c = 0; c < C_DIM; c++) { float w = wT[c * WROW + tid]; s = fmaf(w, w, s); }
        wnorm[tid] = s;
    }
    __syncthreads();

    // ---- per-warp persistent tile loop (no CTA barriers inside) ----
    int buf = 0;
    for (int t = cta; t < NTILES; t += NCTAS) {
        // prefetch next tile's slice into the other buffer
        {
            int tn = t + NCTAS; if (tn >= NTILES) tn = 0;
            const float* src = inputs + (size_t)(tn >> 4) * (C_DIM * HW)
                             + (tn & 15) * 64 + 4 * warp;
            uint32_t dst = xw_sa + (uint32_t)((buf ^ 1) * 256) * 4;
            CP_ASYNC16(dst + (uint32_t)(c0 * 4) * 4, src + (size_t)c0 * HW);
            CP_ASYNC16(dst + (uint32_t)(c1 * 4) * 4, src + (size_t)c1 * HW);
            CP_COMMIT();
        }
        CP_WAIT1();                    // this thread's copies for current buffer done
        __syncwarp();                  // all lanes' copies visible warp-wide

        const float* slice = xw_base + buf * 256;   // [c][4] floats

        // xnorm for own rows: lane r (<4) computes row r (sequential fmaf rounding)
        float xn_own = 0.f;
        if (lane < 4) {
            #pragma unroll
            for (int c = 0; c < C_DIM; c++) {
                float x = slice[c * 4 + lane];
                xn_own = fmaf(x, x, xn_own);
            }
        }

        // ---- mainloop: 4 rows x 16 codes per lane; codes k = 2*lane + 64*j ----
        ull acc[4][8];
        #pragma unroll
        for (int r = 0; r < 4; r++)
            #pragma unroll
            for (int j = 0; j < 8; j++) acc[r][j] = 0ULL;

        const ull* bbase = (const ull*)(wT + 2 * lane);

        #pragma unroll 4
        for (int c = 0; c < C_DIM; c++) {
            const float4 av = *(const float4*)(slice + c * 4);   // broadcast
            ull a0 = pack2(av.x), a1 = pack2(av.y), a2 = pack2(av.z), a3 = pack2(av.w);
            const ull* bp = bbase + (size_t)c * (WROW / 2);
            ull bb[8];
            #pragma unroll
            for (int j = 0; j < 8; j++) bb[j] = bp[32 * j];      // conflict-free LDS.64
            #pragma unroll
            for (int j = 0; j < 8; j++) {
                fma2(acc[0][j], a0, bb[j]);
                fma2(acc[1][j], a1, bb[j]);
                fma2(acc[2][j], a2, bb[j]);
                fma2(acc[3][j], a3, bb[j]);
            }
        }

        const int n0   = t * TM + 4 * warp;       // first row owned by this warp
        const int bimg = t >> 4;
        const int p0   = (t & 15) * 64 + 4 * warp;

        // ---- epilogue: distances (reference rounding) + full-K warp argmin ----
        const float INF = __int_as_float(0x7f800000);
        int   bi_r[4];
        #pragma unroll
        for (int r = 0; r < 4; r++) {
            const int n = n0 + r;
            const float xn = __shfl_sync(0xffffffffu, xn_own, r);

            float best = INF; int bidx = 0;
            float* dptr = out + DIST_OFF + (size_t)n * K_CB;
            #pragma unroll
            for (int j = 0; j < 8; j++) {
                float zlo, zhi; unpack2(acc[r][j], zlo, zhi);
                const int k0 = 2 * lane + 64 * j;
                const float2 wn2 = *(const float2*)(wnorm + k0);  // LDS.64 aligned
                float dlo = (xn + wn2.x) - 2.0f * zlo;
                float dhi = (xn + wn2.y) - 2.0f * zhi;
                __stcs(dptr + k0,     dlo);                       // coalesced pairs
                __stcs(dptr + k0 + 1, dhi);
                if (dlo < best) { best = dlo; bidx = k0; }        // ascending k, strict '<'
                if (dhi < best) { best = dhi; bidx = k0 + 1; }    // -> lowest index on ties
            }
            #pragma unroll
            for (int off = 16; off > 0; off >>= 1) {
                float ob = __shfl_xor_sync(0xffffffffu, best, off);
                int   oi = __shfl_xor_sync(0xffffffffu, bidx, off);
                if (ob < best || (ob == best && oi < bidx)) { best = ob; bidx = oi; }
            }
            bi_r[r] = bidx;                                      // all lanes agree
            if (lane == 0) {
                out[EIDX_OFF + (size_t)n] = (float)bidx;
                atomicAdd(&g_hist[bidx], 1);                     // order-independent
            }
        }

        // ---- encodings: blind zero-fill (no compares) then overwrite the 1.0 ----
        {
            float* ebase = out + ENC_OFF + (size_t)n0 * K_CB;
            const float4 z4 = make_float4(0.f, 0.f, 0.f, 0.f);
            #pragma unroll
            for (int r = 0; r < 4; r++) {
                float* rbase = ebase + (size_t)r * K_CB;
                #pragma unroll
                for (int m = lane; m < 127; m += 32)
                    __stcs((float4*)(rbase + 3 + 4 * m), z4);   // 16B aligned interior
                if (lane < 3)       rbase[lane] = 0.f;
                else if (lane == 3) rbase[511]  = 0.f;
            }
            __syncwarp();                  // zero stores ordered before the overwrite
            if (lane < 4) {
                int sv = bi_r[0];                                // lane r -> bi_r[r]
                if (lane == 1) sv = bi_r[1];
                if (lane == 2) sv = bi_r[2];
                if (lane == 3) sv = bi_r[3];
                ebase[(size_t)lane * K_CB + sv] = 1.0f;
            }
        }

        // ---- q_out for own rows (x + (q - x)) + loss partial; 2 c per lane ----
        float s = 0.f;
        float* qbase = out + (size_t)bimg * (C_DIM * HW) + p0;
        #pragma unroll
        for (int cc = 0; cc < 2; cc++) {
            const int c = cc ? c1 : c0;
            float4 x4 = *(const float4*)(slice + c * 4);
            const float* wrow = wT + c * WROW;
            float d0 = wrow[bi_r[0]] - x4.x;
            float d1 = wrow[bi_r[1]] - x4.y;
            float d2 = wrow[bi_r[2]] - x4.z;
            float d3 = wrow[bi_r[3]] - x4.w;
            float4 o;
            o.x = x4.x + d0; o.y = x4.y + d1; o.z = x4.z + d2; o.w = x4.w + d3;
            __stcs((float4*)(qbase + (size_t)c * HW), o);        // 16B aligned
            s = fmaf(d0, d0, s); s = fmaf(d1, d1, s);
            s = fmaf(d2, d2, s); s = fmaf(d3, d3, s);
        }
        #pragma unroll
        for (int off = 16; off > 0; off >>= 1) s += __shfl_xor_sync(0xffffffffu, s, off);
        if (lane == 0) g_lp[t * NWARP + warp] = s;

        __syncwarp();                  // slice reads done before next-iter prefetch reuse
        buf ^= 1;
    }
    CP_WAIT0();                        // drain dangling prefetch

    // ---- fused finish: last CTA computes loss + perplexity ----
    __syncthreads();
    __shared__ int s_last;
    if (tid == 0) {
        __threadfence();
        s_last = (atomicAdd(&g_done, 1) == NCTAS - 1);
    }
    __syncthreads();
    if (s_last) {
        if (tid == 0) g_done = 0;                 // reset for graph replay
        if (tid < B_DIM) {
            float s = 0.f;
            #pragma unroll
            for (int j = 0; j < 16; j++)          // tiles of batch, fixed order
                #pragma unroll
                for (int w = 0; w < NWARP; w++)   // warp partials, fixed order
                    s += g_lp[(tid * 16 + j) * NWARP + w];
            out[LOSS_OFF + tid] = 1.25f * (s * (1.0f / 65536.0f));
        }
        int h = g_hist[tid];
        g_hist[tid] = 0;                          // restore zero invariant
        float p = (float)h * (1.0f / 65536.0f);
        red[tid] = -p * logf(p + 1e-10f);
        __syncthreads();
        #pragma unroll
        for (int off = 256; off > 0; off >>= 1) {
            if (tid < off) red[tid] += red[tid + off];
            __syncthreads();
        }
        if (tid == 0) out[PERP_OFF] = expf(red[0]);
    }
}

// ---------------- launch ----------------
extern "C" void kernel_launch(void* const* d_in, const int* in_sizes, int n_in,
                              void* d_out, int out_size)
{
    const float* inputs = (const float*)d_in[0];
    const float* weight = (const float*)d_in[1];
    float* out = (float*)d_out;

    if (out_size != OUT_TOTAL) return;

    cudaFuncSetAttribute(vq_all, cudaFuncAttributeMaxDynamicSharedMemorySize, SMEM_BYTES);

    vq_all<<<NCTAS, THREADS, SMEM_BYTES>>>(inputs, weight, out);
}